// round 2
// baseline (speedup 1.0000x reference)
#include <cuda_runtime.h>
#include <cuda_bf16.h>
#include <cstdint>
#include <cstddef>

#define S_LEN 512
#define BATCH 64
#define EDIM  512
#define HDIM  1024
#define G4    4096
#define NTAGS 13
#define DFF   256
#define NCTA_SEQ 64

// ---------------- persistent device scratch (no allocs allowed) ----------------
__device__ __align__(16) __nv_bfloat16 g_Wih[(size_t)NTAGS * G4 * EDIM];   // 54.5 MB
__device__ __align__(16) __nv_bfloat16 g_Whh[(size_t)NTAGS * G4 * HDIM];   // 109 MB (L2-resident)
__device__ float g_bias[NTAGS * G4];
__device__ __align__(16) __nv_bfloat16 g_x[(size_t)S_LEN * BATCH * EDIM];  // 33.5 MB
__device__ float g_X[(size_t)S_LEN * G4 * BATCH];                          // 537 MB input gates
__device__ __align__(16) __nv_bfloat16 g_h[BATCH * HDIM];
__device__ float g_hf[BATCH * HDIM];
__device__ unsigned g_bar;

// ---------------- helpers ----------------
__device__ __forceinline__ unsigned smem_u32(const void* p) {
    return (unsigned)__cvta_generic_to_shared(p);
}
__device__ __forceinline__ void cp16(unsigned s, const void* g) {
    asm volatile("cp.async.cg.shared.global [%0], [%1], 16;" :: "r"(s), "l"(g));
}
__device__ __forceinline__ void cp_commit() { asm volatile("cp.async.commit_group;" ::: "memory"); }
__device__ __forceinline__ void cp_wait1()  { asm volatile("cp.async.wait_group 1;" ::: "memory"); }
__device__ __forceinline__ void cp_wait0()  { asm volatile("cp.async.wait_group 0;" ::: "memory"); }

__device__ __forceinline__ void ldsm4(unsigned& r0, unsigned& r1, unsigned& r2, unsigned& r3, unsigned a) {
    asm volatile("ldmatrix.sync.aligned.m8n8.x4.shared.b16 {%0,%1,%2,%3}, [%4];"
                 : "=r"(r0), "=r"(r1), "=r"(r2), "=r"(r3) : "r"(a));
}
__device__ __forceinline__ void mma16816(float* c, unsigned a0, unsigned a1, unsigned a2, unsigned a3,
                                         unsigned b0, unsigned b1) {
    asm volatile("mma.sync.aligned.m16n8k16.row.col.f32.bf16.bf16.f32 "
                 "{%0,%1,%2,%3},{%4,%5,%6,%7},{%8,%9},{%0,%1,%2,%3};"
                 : "+f"(c[0]), "+f"(c[1]), "+f"(c[2]), "+f"(c[3])
                 : "r"(a0), "r"(a1), "r"(a2), "r"(a3), "r"(b0), "r"(b1));
}
__device__ __forceinline__ float sigf(float x) { return 1.f / (1.f + __expf(-x)); }

__device__ __forceinline__ uint2 f4_to_bf4(float4 v) {
    __nv_bfloat162 a = __floats2bfloat162_rn(v.x, v.y);
    __nv_bfloat162 b = __floats2bfloat162_rn(v.z, v.w);
    uint2 r;
    r.x = *reinterpret_cast<unsigned*>(&a);
    r.y = *reinterpret_cast<unsigned*>(&b);
    return r;
}

// ---------------- K1: weight conversion + state init ----------------
__global__ void k_prep(const float4* __restrict__ Wih, const float4* __restrict__ Whh,
                       const float* __restrict__ bih, const float* __restrict__ bhh) {
    size_t i0 = (size_t)blockIdx.x * blockDim.x + threadIdx.x;
    size_t stp = (size_t)gridDim.x * blockDim.x;
    uint2* wo = (uint2*)g_Wih;
    for (size_t i = i0; i < (size_t)NTAGS * G4 * EDIM / 4; i += stp) wo[i] = f4_to_bf4(__ldg(Wih + i));
    uint2* ho = (uint2*)g_Whh;
    for (size_t i = i0; i < (size_t)NTAGS * G4 * HDIM / 4; i += stp) ho[i] = f4_to_bf4(__ldg(Whh + i));
    for (size_t i = i0; i < (size_t)NTAGS * G4; i += stp) g_bias[i] = bih[i] + bhh[i];
    for (size_t i = i0; i < (size_t)BATCH * HDIM; i += stp) g_h[i] = __float2bfloat16(0.f);
    if (i0 == 0) g_bar = 0u;
}

// ---------------- K2: embedding gather -> bf16 [S][B][E] ----------------
__global__ void k_embed(const int* __restrict__ tokens, const float* __restrict__ emb) {
    const int s = blockIdx.x, b = blockIdx.y;
    const int tok = __ldg(tokens + b * S_LEN + s);
    float4 v = __ldg((const float4*)(emb + (size_t)tok * EDIM) + threadIdx.x);
    ((uint2*)(g_x + ((size_t)s * BATCH + b) * EDIM))[threadIdx.x] = f4_to_bf4(v);
}

// ---------------- K3: X[s][gate_row][b] = W_ih[tag_s] @ x_s^T + bias ----------------
__global__ void __launch_bounds__(256) k_xgemm(const int* __restrict__ tags) {
    __shared__ __align__(16) __nv_bfloat16 As[2][64][72];  // W_ih rows (M = gate rows)
    __shared__ __align__(16) __nv_bfloat16 Bs[2][64][72];  // x batch rows (N = batch)
    const int s = blockIdx.y, rt = blockIdx.x;
    const int tid = threadIdx.x, lane = tid & 31, wid = tid >> 5;
    const int tag = __ldg(tags + s);
    const __nv_bfloat16* __restrict__ Wb = g_Wih + ((size_t)tag * G4 + rt * 64) * EDIM;
    const __nv_bfloat16* __restrict__ xb = g_x + (size_t)s * BATCH * EDIM;

    const __nv_bfloat16* gsrc[4]; unsigned sdst[4];
#pragma unroll
    for (int t = 0; t < 4; t++) {
        int o = tid + 256 * t;
        if (o < 512) { int r = o >> 3, sg = o & 7; gsrc[t] = Wb + (size_t)r * EDIM + sg * 8; sdst[t] = smem_u32(&As[0][r][sg * 8]); }
        else { int o2 = o - 512, r = o2 >> 3, sg = o2 & 7; gsrc[t] = xb + (size_t)r * EDIM + sg * 8; sdst[t] = smem_u32(&Bs[0][r][sg * 8]); }
    }
#pragma unroll
    for (int t = 0; t < 4; t++) cp16(sdst[t], gsrc[t]);
    cp_commit();

    const int lr = lane & 15, lc8 = (lane >> 4) * 8;
    const int wm = (wid & 3) * 16, wn = (wid >> 2) * 32;
    const unsigned aB  = smem_u32(&As[0][wm + lr][lc8]);
    const unsigned bB0 = smem_u32(&Bs[0][wn + lr][lc8]);
    const unsigned bB1 = smem_u32(&Bs[0][wn + 16 + lr][lc8]);
    float acc[4][4] = {};
    for (int kc = 0; kc < 8; kc++) {
        if (kc < 7) {
#pragma unroll
            for (int t = 0; t < 4; t++) cp16(sdst[t] + ((kc + 1) & 1) * 9216u, gsrc[t] + (kc + 1) * 64);
            cp_commit(); cp_wait1();
        } else cp_wait0();
        __syncthreads();
        unsigned boff = (kc & 1) * 9216u;
#pragma unroll
        for (int kk = 0; kk < 4; kk++) {
            unsigned ko = boff + kk * 32u;
            unsigned a0,a1,a2,a3,p0,p1,p2,p3,q0,q1,q2,q3;
            ldsm4(a0,a1,a2,a3, aB + ko);
            ldsm4(p0,p1,p2,p3, bB0 + ko);
            ldsm4(q0,q1,q2,q3, bB1 + ko);
            mma16816(acc[0], a0,a1,a2,a3, p0,p2);
            mma16816(acc[1], a0,a1,a2,a3, p1,p3);
            mma16816(acc[2], a0,a1,a2,a3, q0,q2);
            mma16816(acc[3], a0,a1,a2,a3, q1,q3);
        }
        __syncthreads();
    }
    const int r0 = rt * 64 + wm + (lane >> 2);      // gate row (M)
    const int c0 = wn + (lane & 3) * 2;             // batch (N)
    const float bb0 = g_bias[tag * G4 + r0];
    const float bb1 = g_bias[tag * G4 + r0 + 8];
    size_t base = (size_t)s * G4;
#pragma unroll
    for (int nt = 0; nt < 4; nt++) {
        int cc = c0 + nt * 8;
        *(float2*)&g_X[(base + r0) * BATCH + cc]     = make_float2(acc[nt][0] + bb0, acc[nt][1] + bb0);
        *(float2*)&g_X[(base + r0 + 8) * BATCH + cc] = make_float2(acc[nt][2] + bb1, acc[nt][3] + bb1);
    }
}

// ---------------- K4: persistent sequential LSTM (64 CTAs, grid barrier/step) ----------------
__global__ void __launch_bounds__(256) k_seq(const int* __restrict__ tags) {
    __shared__ __align__(16) __nv_bfloat16 As[2][64][72];  // h rows (M = batch)
    __shared__ __align__(16) __nv_bfloat16 Bs[2][64][72];  // W_hh rows (N = 64 gate rows)
    float (*gates)[68] = reinterpret_cast<float(*)[68]>(&As[0][0][0]);  // overlay, used post-MMA
    const int tid = threadIdx.x, lane = tid & 31, wid = tid >> 5;
    const int j0 = blockIdx.x * 16;                 // this CTA's 16 h-columns

    bool isA[4]; size_t goff[4]; unsigned sdst[4];
#pragma unroll
    for (int t = 0; t < 4; t++) {
        int o = tid + 256 * t;
        if (o < 512) {
            int r = o >> 3, sg = o & 7;
            isA[t] = true; goff[t] = (size_t)r * HDIM + sg * 8;
            sdst[t] = smem_u32(&As[0][r][sg * 8]);
        } else {
            int o2 = o - 512, r = o2 >> 3, sg = o2 & 7;
            int grow = j0 + (r & 15) + (r >> 4) * HDIM;   // rows: i(0-15) f g o sections
            isA[t] = false; goff[t] = (size_t)grow * HDIM + sg * 8;
            sdst[t] = smem_u32(&Bs[0][r][sg * 8]);
        }
    }
    const int lr = lane & 15, lc8 = (lane >> 4) * 8;
    const int wm = (wid & 3) * 16, wn = (wid >> 2) * 32;
    const unsigned aB  = smem_u32(&As[0][wm + lr][lc8]);
    const unsigned bB0 = smem_u32(&Bs[0][wn + lr][lc8]);
    const unsigned bB1 = smem_u32(&Bs[0][wn + 16 + lr][lc8]);

    const int eb = tid & 63;          // epilogue batch
    const int jb = (tid >> 6) * 4;    // epilogue column base (0,4,8,12)
    float cst[4] = {0.f, 0.f, 0.f, 0.f};

    for (int s = 0; s < S_LEN; s++) {
        const int tag = __ldg(tags + s);
        const __nv_bfloat16* __restrict__ Wb = g_Whh + (size_t)tag * G4 * HDIM;

        // prefetch this step's X gates into registers (overlaps MMA loop)
        float xg[4][4];
        {
            const float* Xs = g_X + (size_t)s * G4 * BATCH;
#pragma unroll
            for (int q = 0; q < 4; q++) {
                size_t xb = (size_t)(j0 + jb + q) * BATCH + eb;
#pragma unroll
                for (int sec = 0; sec < 4; sec++)
                    xg[sec][q] = __ldg(Xs + xb + (size_t)sec * HDIM * BATCH);
            }
        }

#pragma unroll
        for (int t = 0; t < 4; t++) cp16(sdst[t], (isA[t] ? (const __nv_bfloat16*)g_h : Wb) + goff[t]);
        cp_commit();
        float acc[4][4] = {};
        for (int kc = 0; kc < 16; kc++) {
            if (kc < 15) {
#pragma unroll
                for (int t = 0; t < 4; t++)
                    cp16(sdst[t] + ((kc + 1) & 1) * 9216u,
                         (isA[t] ? (const __nv_bfloat16*)g_h : Wb) + goff[t] + (kc + 1) * 64);
                cp_commit(); cp_wait1();
            } else cp_wait0();
            __syncthreads();
            unsigned boff = (kc & 1) * 9216u;
#pragma unroll
            for (int kk = 0; kk < 4; kk++) {
                unsigned ko = boff + kk * 32u;
                unsigned a0,a1,a2,a3,p0,p1,p2,p3,q0,q1,q2,q3;
                ldsm4(a0,a1,a2,a3, aB + ko);
                ldsm4(p0,p1,p2,p3, bB0 + ko);
                ldsm4(q0,q1,q2,q3, bB1 + ko);
                mma16816(acc[0], a0,a1,a2,a3, p0,p2);
                mma16816(acc[1], a0,a1,a2,a3, p1,p3);
                mma16816(acc[2], a0,a1,a2,a3, q0,q2);
                mma16816(acc[3], a0,a1,a2,a3, q1,q3);
            }
            __syncthreads();
        }
        // stash W_hh*h into smem gates[gate_row_local][batch]
        {
            const int bO = wm + (lane >> 2);
            const int rO = wn + (lane & 3) * 2;
#pragma unroll
            for (int nt = 0; nt < 4; nt++) {
                int n = rO + nt * 8;
                gates[n][bO]         = acc[nt][0];
                gates[n + 1][bO]     = acc[nt][1];
                gates[n][bO + 8]     = acc[nt][2];
                gates[n + 1][bO + 8] = acc[nt][3];
            }
        }
        __syncthreads();
        // epilogue: gate nonlinearities + state update (4 (b,col) cells per thread)
        {
            __nv_bfloat16 hb[4];
            float hv[4];
#pragma unroll
            for (int q = 0; q < 4; q++) {
                int col = jb + q;
                float gi = gates[col][eb]      + xg[0][q];
                float gf = gates[col + 16][eb] + xg[1][q];
                float gg = gates[col + 32][eb] + xg[2][q];
                float go = gates[col + 48][eb] + xg[3][q];
                float c = sigf(gf) * cst[q] + sigf(gi) * tanhf(gg);
                cst[q] = c;
                float h = sigf(go) * tanhf(c);
                hv[q] = h;
                hb[q] = __float2bfloat16(h);
            }
            *(uint2*)&g_h[eb * HDIM + j0 + jb] = *(uint2*)hb;
            if (s == S_LEN - 1)
                *(float4*)&g_hf[eb * HDIM + j0 + jb] = make_float4(hv[0], hv[1], hv[2], hv[3]);
        }
        __syncthreads();
        // software grid barrier (monotonic counter; 64 CTAs all resident)
        if (tid == 0) {
            __threadfence();
            unsigned target = (unsigned)(s + 1) * NCTA_SEQ;
            unsigned arrived = atomicAdd(&g_bar, 1u) + 1u;
            if (arrived < target) {
                unsigned v;
                do {
                    asm volatile("ld.global.acquire.gpu.u32 %0, [%1];" : "=r"(v) : "l"(&g_bar));
                } while (v < target);
            }
        }
        __syncthreads();
    }
}

// ---------------- K5: MLP head ----------------
__global__ void k_mlp(const float* __restrict__ W1, const float* __restrict__ b1,
                      const float* __restrict__ W2, const float* __restrict__ b2,
                      float* __restrict__ out) {
    __shared__ float red[DFF];
    const int b = blockIdx.x, d = threadIdx.x;
    const float4* h4 = (const float4*)(g_hf + (size_t)b * HDIM);
    const float4* w4 = (const float4*)(W1 + (size_t)d * HDIM);
    float s = 0.f;
#pragma unroll 4
    for (int k = 0; k < HDIM / 4; k++) {
        float4 a = h4[k], w = __ldg(w4 + k);
        s += a.x * w.x + a.y * w.y + a.z * w.z + a.w * w.w;
    }
    float hid = fmaxf(s + __ldg(b1 + d), 0.f);
    red[d] = hid * __ldg(W2 + d);
    __syncthreads();
    for (int st = DFF / 2; st > 0; st >>= 1) {
        if (d < st) red[d] += red[d + st];
        __syncthreads();
    }
    if (d == 0) out[b] = sigf(red[0] + __ldg(b2));
}

// ---------------- launch ----------------
extern "C" void kernel_launch(void* const* d_in, const int* in_sizes, int n_in,
                              void* d_out, int out_size) {
    const int*   tokens = (const int*)d_in[0];
    const int*   tags   = (const int*)d_in[1];
    const float* emb    = (const float*)d_in[2];
    const float* Wih    = (const float*)d_in[3];
    const float* Whh    = (const float*)d_in[4];
    const float* bih    = (const float*)d_in[5];
    const float* bhh    = (const float*)d_in[6];
    const float* W1     = (const float*)d_in[7];
    const float* b1     = (const float*)d_in[8];
    const float* W2     = (const float*)d_in[9];
    const float* b2     = (const float*)d_in[10];
    float* out = (float*)d_out;

    k_prep<<<2048, 256>>>((const float4*)Wih, (const float4*)Whh, bih, bhh);
    k_embed<<<dim3(S_LEN, BATCH), 128>>>(tokens, emb);
    k_xgemm<<<dim3(64, S_LEN), 256>>>(tags);
    k_seq<<<NCTA_SEQ, 256>>>(tags);
    k_mlp<<<BATCH, DFF>>>(W1, b1, W2, b2, out);
}

// round 3
// speedup vs baseline: 1.1071x; 1.1071x over previous
#include <cuda_runtime.h>
#include <cuda_bf16.h>
#include <cstdint>
#include <cstddef>

#define S_LEN 512
#define BATCH 64
#define EDIM  512
#define HDIM  1024
#define G4    4096
#define NTAGS 13
#define DFF   256
#define NCTA_SEQ 64

// ---------------- persistent device scratch (no allocs allowed) ----------------
__device__ __align__(16) __nv_bfloat16 g_Wih[(size_t)NTAGS * G4 * EDIM];   // 54.5 MB
__device__ __align__(16) __nv_bfloat16 g_Whh[(size_t)NTAGS * G4 * HDIM];   // 109 MB (L2-resident)
__device__ float g_bias[NTAGS * G4];
__device__ __align__(16) __nv_bfloat16 g_x[(size_t)S_LEN * BATCH * EDIM];  // 33.5 MB
__device__ float g_X[(size_t)S_LEN * G4 * BATCH];                          // 537 MB input gates
__device__ __align__(16) __nv_bfloat16 g_h[BATCH * HDIM];
__device__ float g_hf[BATCH * HDIM];
__device__ int g_order[S_LEN];
__device__ unsigned g_bar;

// ---------------- helpers ----------------
__device__ __forceinline__ unsigned smem_u32(const void* p) {
    return (unsigned)__cvta_generic_to_shared(p);
}
__device__ __forceinline__ void cp16(unsigned s, const void* g) {
    asm volatile("cp.async.cg.shared.global [%0], [%1], 16;" :: "r"(s), "l"(g));
}
__device__ __forceinline__ void cp_commit() { asm volatile("cp.async.commit_group;" ::: "memory"); }
__device__ __forceinline__ void cp_wait2()  { asm volatile("cp.async.wait_group 2;" ::: "memory"); }
__device__ __forceinline__ void cp_wait1()  { asm volatile("cp.async.wait_group 1;" ::: "memory"); }
__device__ __forceinline__ void cp_wait0()  { asm volatile("cp.async.wait_group 0;" ::: "memory"); }

__device__ __forceinline__ void ldsm4(unsigned& r0, unsigned& r1, unsigned& r2, unsigned& r3, unsigned a) {
    asm volatile("ldmatrix.sync.aligned.m8n8.x4.shared.b16 {%0,%1,%2,%3}, [%4];"
                 : "=r"(r0), "=r"(r1), "=r"(r2), "=r"(r3) : "r"(a));
}
__device__ __forceinline__ void mma16816(float* c, unsigned a0, unsigned a1, unsigned a2, unsigned a3,
                                         unsigned b0, unsigned b1) {
    asm volatile("mma.sync.aligned.m16n8k16.row.col.f32.bf16.bf16.f32 "
                 "{%0,%1,%2,%3},{%4,%5,%6,%7},{%8,%9},{%0,%1,%2,%3};"
                 : "+f"(c[0]), "+f"(c[1]), "+f"(c[2]), "+f"(c[3])
                 : "r"(a0), "r"(a1), "r"(a2), "r"(a3), "r"(b0), "r"(b1));
}
__device__ __forceinline__ float sigf(float x) { return 1.f / (1.f + __expf(-x)); }

__device__ __forceinline__ uint2 f4_to_bf4(float4 v) {
    __nv_bfloat162 a = __floats2bfloat162_rn(v.x, v.y);
    __nv_bfloat162 b = __floats2bfloat162_rn(v.z, v.w);
    uint2 r;
    r.x = *reinterpret_cast<unsigned*>(&a);
    r.y = *reinterpret_cast<unsigned*>(&b);
    return r;
}

// ---------------- K1: weight conversion + state init ----------------
__global__ void k_prep(const float4* __restrict__ Wih, const float4* __restrict__ Whh,
                       const float* __restrict__ bih, const float* __restrict__ bhh) {
    size_t i0 = (size_t)blockIdx.x * blockDim.x + threadIdx.x;
    size_t stp = (size_t)gridDim.x * blockDim.x;
    uint2* wo = (uint2*)g_Wih;
    for (size_t i = i0; i < (size_t)NTAGS * G4 * EDIM / 4; i += stp) wo[i] = f4_to_bf4(__ldg(Wih + i));
    uint2* ho = (uint2*)g_Whh;
    for (size_t i = i0; i < (size_t)NTAGS * G4 * HDIM / 4; i += stp) ho[i] = f4_to_bf4(__ldg(Whh + i));
    for (size_t i = i0; i < (size_t)NTAGS * G4; i += stp) g_bias[i] = bih[i] + bhh[i];
    for (size_t i = i0; i < (size_t)BATCH * HDIM; i += stp) g_h[i] = __float2bfloat16(0.f);
    if (i0 == 0) g_bar = 0u;
}

// ---------------- K1b: stable counting sort of steps by tag ----------------
__global__ void k_order(const int* __restrict__ tags) {
    __shared__ int st[S_LEN];
    int t = threadIdx.x;
    st[t] = tags[t];
    __syncthreads();
    int mytag = st[t];
    int rank = 0;
    for (int j = 0; j < S_LEN; j++) {
        int tg = st[j];
        if (tg < mytag || (tg == mytag && j < t)) rank++;
    }
    g_order[rank] = t;
}

// ---------------- K2: embedding gather -> bf16 [S][B][E] ----------------
__global__ void k_embed(const int* __restrict__ tokens, const float* __restrict__ emb) {
    const int s = blockIdx.x, b = blockIdx.y;
    const int tok = __ldg(tokens + b * S_LEN + s);
    float4 v = __ldg((const float4*)(emb + (size_t)tok * EDIM) + threadIdx.x);
    ((uint2*)(g_x + ((size_t)s * BATCH + b) * EDIM))[threadIdx.x] = f4_to_bf4(v);
}

// ---------------- K3: X[s][gate_row][b] = W_ih[tag_s] @ x_s^T + bias (tag-sorted) ----------------
__global__ void __launch_bounds__(256) k_xgemm(const int* __restrict__ tags) {
    __shared__ __align__(16) __nv_bfloat16 As[2][64][72];  // W_ih rows (M = gate rows)
    __shared__ __align__(16) __nv_bfloat16 Bs[2][64][72];  // x batch rows (N = batch)
    const int s = g_order[blockIdx.y];
    const int rt = blockIdx.x;
    const int tid = threadIdx.x, lane = tid & 31, wid = tid >> 5;
    const int tag = __ldg(tags + s);
    const __nv_bfloat16* __restrict__ Wb = g_Wih + ((size_t)tag * G4 + rt * 64) * EDIM;
    const __nv_bfloat16* __restrict__ xb = g_x + (size_t)s * BATCH * EDIM;

    const __nv_bfloat16* gsrc[4]; unsigned sdst[4];
#pragma unroll
    for (int t = 0; t < 4; t++) {
        int o = tid + 256 * t;
        if (o < 512) { int r = o >> 3, sg = o & 7; gsrc[t] = Wb + (size_t)r * EDIM + sg * 8; sdst[t] = smem_u32(&As[0][r][sg * 8]); }
        else { int o2 = o - 512, r = o2 >> 3, sg = o2 & 7; gsrc[t] = xb + (size_t)r * EDIM + sg * 8; sdst[t] = smem_u32(&Bs[0][r][sg * 8]); }
    }
#pragma unroll
    for (int t = 0; t < 4; t++) cp16(sdst[t], gsrc[t]);
    cp_commit();

    const int lr = lane & 15, lc8 = (lane >> 4) * 8;
    const int wm = (wid & 3) * 16, wn = (wid >> 2) * 32;
    const unsigned aB  = smem_u32(&As[0][wm + lr][lc8]);
    const unsigned bB0 = smem_u32(&Bs[0][wn + lr][lc8]);
    const unsigned bB1 = smem_u32(&Bs[0][wn + 16 + lr][lc8]);
    float acc[4][4] = {};
    for (int kc = 0; kc < 8; kc++) {
        if (kc < 7) {
#pragma unroll
            for (int t = 0; t < 4; t++) cp16(sdst[t] + ((kc + 1) & 1) * 9216u, gsrc[t] + (kc + 1) * 64);
            cp_commit(); cp_wait1();
        } else cp_wait0();
        __syncthreads();
        unsigned boff = (kc & 1) * 9216u;
#pragma unroll
        for (int kk = 0; kk < 4; kk++) {
            unsigned ko = boff + kk * 32u;
            unsigned a0,a1,a2,a3,p0,p1,p2,p3,q0,q1,q2,q3;
            ldsm4(a0,a1,a2,a3, aB + ko);
            ldsm4(p0,p1,p2,p3, bB0 + ko);
            ldsm4(q0,q1,q2,q3, bB1 + ko);
            mma16816(acc[0], a0,a1,a2,a3, p0,p2);
            mma16816(acc[1], a0,a1,a2,a3, p1,p3);
            mma16816(acc[2], a0,a1,a2,a3, q0,q2);
            mma16816(acc[3], a0,a1,a2,a3, q1,q3);
        }
        __syncthreads();
    }
    const int r0 = rt * 64 + wm + (lane >> 2);      // gate row (M)
    const int c0 = wn + (lane & 3) * 2;             // batch (N)
    const float bb0 = g_bias[tag * G4 + r0];
    const float bb1 = g_bias[tag * G4 + r0 + 8];
    size_t base = (size_t)s * G4;
#pragma unroll
    for (int nt = 0; nt < 4; nt++) {
        int cc = c0 + nt * 8;
        *(float2*)&g_X[(base + r0) * BATCH + cc]     = make_float2(acc[nt][0] + bb0, acc[nt][1] + bb0);
        *(float2*)&g_X[(base + r0 + 8) * BATCH + cc] = make_float2(acc[nt][2] + bb1, acc[nt][3] + bb1);
    }
}

// ---------------- K4: persistent sequential LSTM ----------------
// 64 CTAs, 256 threads. 2m x 2n warp grid (32x32 warp tiles), 2-way K-split.
// 8-stage cp.async pipeline over 16 k-chunks (as 8 pairs), 1 syncthreads/pair.
// W_hh + X prefetch for step s+1 issued BEFORE the grid barrier (h-independent).
#define SEQ_SMEM_BYTES (8 * 9216 * 2 + 64 * 68 * 4)
__global__ void __launch_bounds__(256) k_seq(const int* __restrict__ tags) {
    extern __shared__ __align__(16) unsigned char dynsm[];
    __nv_bfloat16* As = (__nv_bfloat16*)dynsm;                 // [8][64][72]
    __nv_bfloat16* Bs = As + 8 * 64 * 72;                      // [8][64][72]
    float* gates = (float*)(Bs + 8 * 64 * 72);                 // [64][68]

    const int tid = threadIdx.x, lane = tid & 31, wid = tid >> 5;
    const int j0 = blockIdx.x * 16;
    const int kg = wid >> 2;                  // k-split group (0/1)
    const int wq = wid & 3;
    const int wm = (wq & 1) * 32, wn = (wq >> 1) * 32;

    // cp transfer mapping: each thread moves 32B (two cp16) per stage per region
    const int idx = tid * 2;
    const int rT = idx >> 3, sgT = idx & 7;
    const unsigned dA = smem_u32(As + rT * 72 + sgT * 8);
    const unsigned dB = smem_u32(Bs + rT * 72 + sgT * 8);
    const __nv_bfloat16* hRow = g_h + (size_t)rT * HDIM + sgT * 8;
    const size_t wOffB = ((size_t)(j0 + (rT & 15)) + (size_t)(rT >> 4) * HDIM) * HDIM + sgT * 8;

    const int lr = lane & 15, lc8 = (lane >> 4) * 8;
    const unsigned aLo = smem_u32(As + (wm + lr) * 72 + lc8);
    const unsigned aHi = aLo + 16 * 72 * 2;
    const unsigned bLo = smem_u32(Bs + (wn + lr) * 72 + lc8);
    const unsigned bHi = bLo + 16 * 72 * 2;

    const int eb = tid & 63;          // epilogue batch
    const int jb = (tid >> 6) * 4;    // epilogue column base
    float cst[4] = {0.f, 0.f, 0.f, 0.f};

    const __nv_bfloat16* WbRow = g_Whh + (size_t)__ldg(tags) * G4 * HDIM + wOffB;

    auto issueW = [&](int pr) {
#pragma unroll
        for (int st2 = 0; st2 < 2; st2++) {
            int kc = 2 * pr + st2;
            unsigned d = dB + (unsigned)(kc & 7) * 9216u;
            const __nv_bfloat16* sp = WbRow + kc * 64;
            cp16(d, sp); cp16(d + 16, sp + 8);
        }
    };
    auto issueA = [&](int pr) {
#pragma unroll
        for (int st2 = 0; st2 < 2; st2++) {
            int kc = 2 * pr + st2;
            unsigned d = dA + (unsigned)(kc & 7) * 9216u;
            const __nv_bfloat16* sp = hRow + kc * 64;
            cp16(d, sp); cp16(d + 16, sp + 8);
        }
    };

    // prologue: W pairs 0..2, A pairs 0..1 (h ready from k_prep)
    issueW(0); cp_commit();
    issueW(1); cp_commit();
    issueW(2); cp_commit();
    issueA(0); cp_commit();
    issueA(1); cp_commit();

    float xg[4][4];
    {
        const float* Xs = g_X;
#pragma unroll
        for (int q = 0; q < 4; q++) {
            size_t xb = (size_t)(j0 + jb + q) * BATCH + eb;
#pragma unroll
            for (int sec = 0; sec < 4; sec++)
                xg[sec][q] = __ldg(Xs + xb + (size_t)sec * HDIM * BATCH);
        }
    }

#pragma unroll 1
    for (int s = 0; s < S_LEN; s++) {
        float acc[2][4][4];
#pragma unroll
        for (int a = 0; a < 2; a++)
#pragma unroll
            for (int b = 0; b < 4; b++)
#pragma unroll
                for (int c = 0; c < 4; c++) acc[a][b][c] = 0.f;

#pragma unroll 1
        for (int pr = 0; pr < 8; pr++) {
            // issue pair pr+2 (slot of pair pr-2, free since sync of iter pr-1)
            if (pr == 0) { issueA(2); cp_commit(); }
            else if (pr <= 5) { issueA(pr + 2); issueW(pr + 2); cp_commit(); }
            if (pr <= 5) cp_wait2(); else if (pr == 6) cp_wait1(); else cp_wait0();
            __syncthreads();
            // compute my k-chunk of this pair
            const int kc = 2 * pr + kg;
            const unsigned so = (unsigned)(kc & 7) * 9216u;
#pragma unroll
            for (int kk = 0; kk < 4; kk++) {
                unsigned ko = so + kk * 32u;
                unsigned l0,l1,l2,l3, h0,h1,h2,h3, p0,p1,p2,p3, q0,q1,q2,q3;
                ldsm4(l0,l1,l2,l3, aLo + ko);
                ldsm4(h0,h1,h2,h3, aHi + ko);
                ldsm4(p0,p1,p2,p3, bLo + ko);
                ldsm4(q0,q1,q2,q3, bHi + ko);
                mma16816(acc[0][0], l0,l1,l2,l3, p0,p2);
                mma16816(acc[0][1], l0,l1,l2,l3, p1,p3);
                mma16816(acc[0][2], l0,l1,l2,l3, q0,q2);
                mma16816(acc[0][3], l0,l1,l2,l3, q1,q3);
                mma16816(acc[1][0], h0,h1,h2,h3, p0,p2);
                mma16816(acc[1][1], h0,h1,h2,h3, p1,p3);
                mma16816(acc[1][2], h0,h1,h2,h3, q0,q2);
                mma16816(acc[1][3], h0,h1,h2,h3, q1,q3);
            }
        }

        // K-split reduction via gates smem: kg1 stores, kg0 adds
        if (kg == 1) {
#pragma unroll
            for (int mt = 0; mt < 2; mt++)
#pragma unroll
                for (int nb = 0; nb < 4; nb++) {
                    int b0 = wm + mt * 16 + (lane >> 2);
                    int n0 = wn + nb * 8 + (lane & 3) * 2;
                    float* gp = &gates[n0 * 68 + b0];
                    gp[0]  = acc[mt][nb][0];
                    gp[68] = acc[mt][nb][1];
                    gp[8]  = acc[mt][nb][2];
                    gp[76] = acc[mt][nb][3];
                }
        }
        __syncthreads();
        if (kg == 0) {
#pragma unroll
            for (int mt = 0; mt < 2; mt++)
#pragma unroll
                for (int nb = 0; nb < 4; nb++) {
                    int b0 = wm + mt * 16 + (lane >> 2);
                    int n0 = wn + nb * 8 + (lane & 3) * 2;
                    float* gp = &gates[n0 * 68 + b0];
                    gp[0]  += acc[mt][nb][0];
                    gp[68] += acc[mt][nb][1];
                    gp[8]  += acc[mt][nb][2];
                    gp[76] += acc[mt][nb][3];
                }
        }
        __syncthreads();

        // epilogue: gate nonlinearities + state update (4 cells/thread)
        {
            __nv_bfloat16 hb[4];
            float hv[4];
#pragma unroll
            for (int q = 0; q < 4; q++) {
                int col = jb + q;
                float gi = gates[col * 68 + eb]        + xg[0][q];
                float gf = gates[(col + 16) * 68 + eb] + xg[1][q];
                float gg = gates[(col + 32) * 68 + eb] + xg[2][q];
                float go = gates[(col + 48) * 68 + eb] + xg[3][q];
                float c = sigf(gf) * cst[q] + sigf(gi) * tanhf(gg);
                cst[q] = c;
                float h = sigf(go) * tanhf(c);
                hv[q] = h;
                hb[q] = __float2bfloat16(h);
            }
            *(uint2*)&g_h[eb * HDIM + j0 + jb] = *(uint2*)hb;
            if (s == S_LEN - 1)
                *(float4*)&g_hf[eb * HDIM + j0 + jb] = make_float4(hv[0], hv[1], hv[2], hv[3]);
        }

        if (s < S_LEN - 1) {
            // pre-barrier: next step's h-independent prefetches (W_hh + X gates)
            const int tagn = __ldg(tags + s + 1);
            WbRow = g_Whh + (size_t)tagn * G4 * HDIM + wOffB;
            issueW(0); cp_commit();
            issueW(1); cp_commit();
            issueW(2); cp_commit();
            {
                const float* Xs = g_X + (size_t)(s + 1) * G4 * BATCH;
#pragma unroll
                for (int q = 0; q < 4; q++) {
                    size_t xb = (size_t)(j0 + jb + q) * BATCH + eb;
#pragma unroll
                    for (int sec = 0; sec < 4; sec++)
                        xg[sec][q] = __ldg(Xs + xb + (size_t)sec * HDIM * BATCH);
                }
            }
            // grid barrier
            if (tid == 0) {
                __threadfence();
                unsigned target = (unsigned)(s + 1) * NCTA_SEQ;
                unsigned arrived = atomicAdd(&g_bar, 1u) + 1u;
                if (arrived < target) {
                    unsigned v;
                    do {
                        asm volatile("ld.global.acquire.gpu.u32 %0, [%1];" : "=r"(v) : "l"(&g_bar));
                    } while (v < target);
                }
            }
            __syncthreads();
            // post-barrier: h-dependent prefetches
            issueA(0); cp_commit();
            issueA(1); cp_commit();
        }
    }
}

// ---------------- K5: MLP head ----------------
__global__ void k_mlp(const float* __restrict__ W1, const float* __restrict__ b1,
                      const float* __restrict__ W2, const float* __restrict__ b2,
                      float* __restrict__ out) {
    __shared__ float red[DFF];
    const int b = blockIdx.x, d = threadIdx.x;
    const float4* h4 = (const float4*)(g_hf + (size_t)b * HDIM);
    const float4* w4 = (const float4*)(W1 + (size_t)d * HDIM);
    float s = 0.f;
#pragma unroll 4
    for (int k = 0; k < HDIM / 4; k++) {
        float4 a = h4[k], w = __ldg(w4 + k);
        s += a.x * w.x + a.y * w.y + a.z * w.z + a.w * w.w;
    }
    float hid = fmaxf(s + __ldg(b1 + d), 0.f);
    red[d] = hid * __ldg(W2 + d);
    __syncthreads();
    for (int st = DFF / 2; st > 0; st >>= 1) {
        if (d < st) red[d] += red[d + st];
        __syncthreads();
    }
    if (d == 0) out[b] = sigf(red[0] + __ldg(b2));
}

// ---------------- launch ----------------
extern "C" void kernel_launch(void* const* d_in, const int* in_sizes, int n_in,
                              void* d_out, int out_size) {
    const int*   tokens = (const int*)d_in[0];
    const int*   tags   = (const int*)d_in[1];
    const float* emb    = (const float*)d_in[2];
    const float* Wih    = (const float*)d_in[3];
    const float* Whh    = (const float*)d_in[4];
    const float* bih    = (const float*)d_in[5];
    const float* bhh    = (const float*)d_in[6];
    const float* W1     = (const float*)d_in[7];
    const float* b1     = (const float*)d_in[8];
    const float* W2     = (const float*)d_in[9];
    const float* b2     = (const float*)d_in[10];
    float* out = (float*)d_out;

    cudaFuncSetAttribute(k_seq, cudaFuncAttributeMaxDynamicSharedMemorySize, SEQ_SMEM_BYTES);

    k_prep<<<2048, 256>>>((const float4*)Wih, (const float4*)Whh, bih, bhh);
    k_order<<<1, S_LEN>>>(tags);
    k_embed<<<dim3(S_LEN, BATCH), 128>>>(tokens, emb);
    k_xgemm<<<dim3(64, S_LEN), 256>>>(tags);
    k_seq<<<NCTA_SEQ, 256, SEQ_SMEM_BYTES>>>(tags);
    k_mlp<<<BATCH, DFF>>>(W1, b1, W2, b2, out);
}

// round 5
// speedup vs baseline: 1.3381x; 1.2087x over previous
#include <cuda_runtime.h>
#include <cuda_bf16.h>
#include <cstdint>
#include <cstddef>

#define S_LEN 512
#define BATCH 64
#define EDIM  512
#define HDIM  1024
#define G4    4096
#define NTAGS 13
#define DFF   256
#define NCTA_SEQ 128

// ---------------- persistent device scratch (no allocs allowed) ----------------
__device__ __align__(16) __nv_bfloat16 g_Wih[(size_t)NTAGS * G4 * EDIM];   // 54.5 MB
__device__ __align__(16) __nv_bfloat16 g_Whh[(size_t)NTAGS * G4 * HDIM];   // 109 MB (L2-resident)
__device__ float g_bias[NTAGS * G4];
__device__ __align__(16) __nv_bfloat16 g_x[(size_t)S_LEN * BATCH * EDIM];  // 33.5 MB
__device__ float g_X[(size_t)S_LEN * G4 * BATCH];                          // 537 MB input gates
__device__ __align__(16) __nv_bfloat16 g_h[BATCH * HDIM];
__device__ float g_hf[BATCH * HDIM];
__device__ int g_order[S_LEN];
__device__ unsigned g_bar;

// ---------------- helpers ----------------
__device__ __forceinline__ unsigned smem_u32(const void* p) {
    return (unsigned)__cvta_generic_to_shared(p);
}
__device__ __forceinline__ void cp16(unsigned s, const void* g) {
    asm volatile("cp.async.cg.shared.global [%0], [%1], 16;" :: "r"(s), "l"(g));
}
__device__ __forceinline__ void cp_commit() { asm volatile("cp.async.commit_group;" ::: "memory"); }
__device__ __forceinline__ void cp_wait2()  { asm volatile("cp.async.wait_group 2;" ::: "memory"); }
__device__ __forceinline__ void cp_wait1()  { asm volatile("cp.async.wait_group 1;" ::: "memory"); }
__device__ __forceinline__ void cp_wait0()  { asm volatile("cp.async.wait_group 0;" ::: "memory"); }

__device__ __forceinline__ void ldsm4(unsigned& r0, unsigned& r1, unsigned& r2, unsigned& r3, unsigned a) {
    asm volatile("ldmatrix.sync.aligned.m8n8.x4.shared.b16 {%0,%1,%2,%3}, [%4];"
                 : "=r"(r0), "=r"(r1), "=r"(r2), "=r"(r3) : "r"(a));
}
__device__ __forceinline__ void mma16816(float* c, unsigned a0, unsigned a1, unsigned a2, unsigned a3,
                                         unsigned b0, unsigned b1) {
    asm volatile("mma.sync.aligned.m16n8k16.row.col.f32.bf16.bf16.f32 "
                 "{%0,%1,%2,%3},{%4,%5,%6,%7},{%8,%9},{%0,%1,%2,%3};"
                 : "+f"(c[0]), "+f"(c[1]), "+f"(c[2]), "+f"(c[3])
                 : "r"(a0), "r"(a1), "r"(a2), "r"(a3), "r"(b0), "r"(b1));
}
__device__ __forceinline__ float sigf(float x) { return 1.f / (1.f + __expf(-x)); }

__device__ __forceinline__ uint2 f4_to_bf4(float4 v) {
    __nv_bfloat162 a = __floats2bfloat162_rn(v.x, v.y);
    __nv_bfloat162 b = __floats2bfloat162_rn(v.z, v.w);
    uint2 r;
    r.x = *reinterpret_cast<unsigned*>(&a);
    r.y = *reinterpret_cast<unsigned*>(&b);
    return r;
}

__device__ __forceinline__ unsigned cluster_rank() {
    unsigned r;
    asm("mov.u32 %0, %%cluster_ctarank;" : "=r"(r));
    return r;
}
__device__ __forceinline__ unsigned mapa_rank(unsigned addr, unsigned r) {
    unsigned out;
    asm("mapa.shared::cluster.u32 %0, %1, %2;" : "=r"(out) : "r"(addr), "r"(r));
    return out;
}
__device__ __forceinline__ void cluster_arrive() { asm volatile("barrier.cluster.arrive.aligned;" ::: "memory"); }
__device__ __forceinline__ void cluster_wait()   { asm volatile("barrier.cluster.wait.aligned;" ::: "memory"); }
__device__ __forceinline__ void dsmem_copy8(unsigned lsrc, unsigned rdst) {
#pragma unroll
    for (int i = 0; i < 4; i++) {
        unsigned long long v;
        asm volatile("ld.shared.b64 %0, [%1];" : "=l"(v) : "r"(lsrc + i * 8));
        asm volatile("st.shared::cluster.b64 [%0], %1;" :: "r"(rdst + i * 8), "l"(v) : "memory");
    }
}

// ---------------- K1: weight conversion + state init ----------------
__global__ void k_prep(const float4* __restrict__ Wih, const float4* __restrict__ Whh,
                       const float* __restrict__ bih, const float* __restrict__ bhh) {
    size_t i0 = (size_t)blockIdx.x * blockDim.x + threadIdx.x;
    size_t stp = (size_t)gridDim.x * blockDim.x;
    uint2* wo = (uint2*)g_Wih;
    for (size_t i = i0; i < (size_t)NTAGS * G4 * EDIM / 4; i += stp) wo[i] = f4_to_bf4(__ldg(Wih + i));
    uint2* ho = (uint2*)g_Whh;
    for (size_t i = i0; i < (size_t)NTAGS * G4 * HDIM / 4; i += stp) ho[i] = f4_to_bf4(__ldg(Whh + i));
    for (size_t i = i0; i < (size_t)NTAGS * G4; i += stp) g_bias[i] = bih[i] + bhh[i];
    for (size_t i = i0; i < (size_t)BATCH * HDIM; i += stp) g_h[i] = __float2bfloat16(0.f);
    if (i0 == 0) g_bar = 0u;
}

// ---------------- K1b: stable counting sort of steps by tag ----------------
__global__ void k_order(const int* __restrict__ tags) {
    __shared__ int st[S_LEN];
    int t = threadIdx.x;
    st[t] = tags[t];
    __syncthreads();
    int mytag = st[t];
    int rank = 0;
    for (int j = 0; j < S_LEN; j++) {
        int tg = st[j];
        if (tg < mytag || (tg == mytag && j < t)) rank++;
    }
    g_order[rank] = t;
}

// ---------------- K2: embedding gather -> bf16 [S][B][E] ----------------
__global__ void k_embed(const int* __restrict__ tokens, const float* __restrict__ emb) {
    const int s = blockIdx.x, b = blockIdx.y;
    const int tok = __ldg(tokens + b * S_LEN + s);
    float4 v = __ldg((const float4*)(emb + (size_t)tok * EDIM) + threadIdx.x);
    ((uint2*)(g_x + ((size_t)s * BATCH + b) * EDIM))[threadIdx.x] = f4_to_bf4(v);
}

// ---------------- K3: X[s][gate_row][b] = W_ih[tag_s] @ x_s^T + bias (tag-sorted) ----------------
__global__ void __launch_bounds__(256) k_xgemm(const int* __restrict__ tags) {
    __shared__ __align__(16) __nv_bfloat16 As[2][64][72];
    __shared__ __align__(16) __nv_bfloat16 Bs[2][64][72];
    const int s = g_order[blockIdx.y];
    const int rt = blockIdx.x;
    const int tid = threadIdx.x, lane = tid & 31, wid = tid >> 5;
    const int tag = __ldg(tags + s);
    const __nv_bfloat16* __restrict__ Wb = g_Wih + ((size_t)tag * G4 + rt * 64) * EDIM;
    const __nv_bfloat16* __restrict__ xb = g_x + (size_t)s * BATCH * EDIM;

    const __nv_bfloat16* gsrc[4]; unsigned sdst[4];
#pragma unroll
    for (int t = 0; t < 4; t++) {
        int o = tid + 256 * t;
        if (o < 512) { int r = o >> 3, sg = o & 7; gsrc[t] = Wb + (size_t)r * EDIM + sg * 8; sdst[t] = smem_u32(&As[0][r][sg * 8]); }
        else { int o2 = o - 512, r = o2 >> 3, sg = o2 & 7; gsrc[t] = xb + (size_t)r * EDIM + sg * 8; sdst[t] = smem_u32(&Bs[0][r][sg * 8]); }
    }
#pragma unroll
    for (int t = 0; t < 4; t++) cp16(sdst[t], gsrc[t]);
    cp_commit();

    const int lr = lane & 15, lc8 = (lane >> 4) * 8;
    const int wm = (wid & 3) * 16, wn = (wid >> 2) * 32;
    const unsigned aB  = smem_u32(&As[0][wm + lr][lc8]);
    const unsigned bB0 = smem_u32(&Bs[0][wn + lr][lc8]);
    const unsigned bB1 = smem_u32(&Bs[0][wn + 16 + lr][lc8]);
    float acc[4][4] = {};
    for (int kc = 0; kc < 8; kc++) {
        if (kc < 7) {
#pragma unroll
            for (int t = 0; t < 4; t++) cp16(sdst[t] + ((kc + 1) & 1) * 9216u, gsrc[t] + (kc + 1) * 64);
            cp_commit(); cp_wait1();
        } else cp_wait0();
        __syncthreads();
        unsigned boff = (kc & 1) * 9216u;
#pragma unroll
        for (int kk = 0; kk < 4; kk++) {
            unsigned ko = boff + kk * 32u;
            unsigned a0,a1,a2,a3,p0,p1,p2,p3,q0,q1,q2,q3;
            ldsm4(a0,a1,a2,a3, aB + ko);
            ldsm4(p0,p1,p2,p3, bB0 + ko);
            ldsm4(q0,q1,q2,q3, bB1 + ko);
            mma16816(acc[0], a0,a1,a2,a3, p0,p2);
            mma16816(acc[1], a0,a1,a2,a3, p1,p3);
            mma16816(acc[2], a0,a1,a2,a3, q0,q2);
            mma16816(acc[3], a0,a1,a2,a3, q1,q3);
        }
        __syncthreads();
    }
    const int r0 = rt * 64 + wm + (lane >> 2);
    const int c0 = wn + (lane & 3) * 2;
    const float bb0 = g_bias[tag * G4 + r0];
    const float bb1 = g_bias[tag * G4 + r0 + 8];
    size_t base = (size_t)s * G4;
#pragma unroll
    for (int nt = 0; nt < 4; nt++) {
        int cc = c0 + nt * 8;
        *(float2*)&g_X[(base + r0) * BATCH + cc]     = make_float2(acc[nt][0] + bb0, acc[nt][1] + bb0);
        *(float2*)&g_X[(base + r0 + 8) * BATCH + cc] = make_float2(acc[nt][2] + bb1, acc[nt][3] + bb1);
    }
}

// ---------------- K4: persistent sequential LSTM ----------------
// 128 CTAs as 64 clusters of 2. Cluster c owns 16 h-columns (64 gate rows);
// rank = K-half (0: k<512, 1: k>=512). 8 warps: 2m x 2n x 2kg, 4 k-pairs/step.
// Partial fp32 gates exchanged via DSMEM (peer batch-half only); epilogue split
// by batch-half across the pair. One global barrier (128 CTAs) per step.
// smem: As 8x9216 | Bs 8x9216 | gates 64x68 f32 | gates2 64x68 f32
#define GATES_OFF  147456
#define GATES2_OFF 164864
#define SEQ_SMEM   182272
__global__ void __launch_bounds__(256) __cluster_dims__(2, 1, 1) k_seq(const int* __restrict__ tags) {
    extern __shared__ __align__(16) unsigned char sm[];
    __nv_bfloat16* As = (__nv_bfloat16*)sm;            // [8][64][72]
    __nv_bfloat16* Bs = As + 8 * 64 * 72;              // [8][64][72]
    float* gates  = (float*)(sm + GATES_OFF);          // [64][68]
    float* gates2 = (float*)(sm + GATES2_OFF);         // [64][68]
    const unsigned smb = smem_u32(sm);

    const int tid = threadIdx.x, lane = tid & 31, wid = tid >> 5;
    const unsigned rank = cluster_rank();
    const unsigned peer = rank ^ 1u;
    const int j0 = (blockIdx.x >> 1) * 16;
    const int koff = (int)rank * 512;
    const int kg = wid >> 2;
    const int wq = wid & 3;
    const int wm = (wq & 1) * 32, wn = (wq >> 1) * 32;

    // cp transfer mapping: each thread moves 32B (two cp16) per chunk per region
    const int idx = tid * 2;
    const int rT = idx >> 3, sgT = idx & 7;
    const unsigned dA = smem_u32(As + rT * 72 + sgT * 8);
    const unsigned dB = smem_u32(Bs + rT * 72 + sgT * 8);
    const __nv_bfloat16* hRow = g_h + (size_t)rT * HDIM + koff + sgT * 8;
    const size_t wOffB = ((size_t)(j0 + (rT & 15)) + (size_t)(rT >> 4) * HDIM) * HDIM + koff + sgT * 8;

    const int lr = lane & 15, lc8 = (lane >> 4) * 8;
    const unsigned aLo = smem_u32(As + (wm + lr) * 72 + lc8);
    const unsigned aHi = aLo + 16 * 72 * 2;
    const unsigned bLo = smem_u32(Bs + (wn + lr) * 72 + lc8);
    const unsigned bHi = bLo + 16 * 72 * 2;

    // DSMEM exchange mapping: copy peer's batch half of my gates into peer's gates2
    const int cn = tid >> 2;                       // gate row 0..63
    const int cb = (int)peer * 32 + (tid & 3) * 8; // 8 batch entries
    const unsigned xsrc = smb + GATES_OFF  + (unsigned)(cn * 68 + cb) * 4;
    const unsigned xdstL = smb + GATES2_OFF + (unsigned)(cn * 68 + cb) * 4;
    const unsigned xdstR = mapa_rank(xdstL, peer);

    // epilogue mapping: this rank handles batches [rank*32, rank*32+32), 2 cols/thread
    const int eb = (int)rank * 32 + (lane);
    const int jb = wid * 2;                        // 0..14
    float cst[2] = {0.f, 0.f};

    const __nv_bfloat16* WbRow = g_Whh + (size_t)__ldg(tags) * G4 * HDIM + wOffB;

    auto issueW = [&](int pr) {
#pragma unroll
        for (int st2 = 0; st2 < 2; st2++) {
            int kc = 2 * pr + st2;
            unsigned d = dB + (unsigned)kc * 9216u;
            const __nv_bfloat16* sp = WbRow + kc * 64;
            cp16(d, sp); cp16(d + 16, sp + 8);
        }
    };
    auto issueA = [&](int pr) {
#pragma unroll
        for (int st2 = 0; st2 < 2; st2++) {
            int kc = 2 * pr + st2;
            unsigned d = dA + (unsigned)kc * 9216u;
            const __nv_bfloat16* sp = hRow + kc * 64;
            cp16(d, sp); cp16(d + 16, sp + 8);
        }
    };

    // prologue
    issueW(0); cp_commit();
    issueW(1); cp_commit();
    issueW(2); cp_commit();
    issueA(0); cp_commit();
    issueA(1); cp_commit();

    float xg[4][2];
    {
        const float* Xs = g_X;
#pragma unroll
        for (int sec = 0; sec < 4; sec++)
#pragma unroll
            for (int q = 0; q < 2; q++)
                xg[sec][q] = __ldg(Xs + ((size_t)sec * HDIM + j0 + jb + q) * BATCH + eb);
    }

#pragma unroll 1
    for (int s = 0; s < S_LEN; s++) {
        float acc[2][4][4];
#pragma unroll
        for (int a = 0; a < 2; a++)
#pragma unroll
            for (int b = 0; b < 4; b++)
#pragma unroll
                for (int c = 0; c < 4; c++) acc[a][b][c] = 0.f;

#pragma unroll 1
        for (int pr = 0; pr < 4; pr++) {
            if (pr == 0) { issueA(2); cp_commit(); }
            else if (pr == 1) { issueA(3); issueW(3); cp_commit(); }
            if (pr <= 1) cp_wait2(); else if (pr == 2) cp_wait1(); else cp_wait0();
            __syncthreads();
            const int kc = 2 * pr + kg;
            const unsigned so = (unsigned)kc * 9216u;
#pragma unroll
            for (int kk = 0; kk < 4; kk++) {
                unsigned ko = so + kk * 32u;
                unsigned l0,l1,l2,l3, h0,h1,h2,h3, p0,p1,p2,p3, q0,q1,q2,q3;
                ldsm4(l0,l1,l2,l3, aLo + ko);
                ldsm4(h0,h1,h2,h3, aHi + ko);
                ldsm4(p0,p1,p2,p3, bLo + ko);
                ldsm4(q0,q1,q2,q3, bHi + ko);
                mma16816(acc[0][0], l0,l1,l2,l3, p0,p2);
                mma16816(acc[0][1], l0,l1,l2,l3, p1,p3);
                mma16816(acc[0][2], l0,l1,l2,l3, q0,q2);
                mma16816(acc[0][3], l0,l1,l2,l3, q1,q3);
                mma16816(acc[1][0], h0,h1,h2,h3, p0,p2);
                mma16816(acc[1][1], h0,h1,h2,h3, p1,p3);
                mma16816(acc[1][2], h0,h1,h2,h3, q0,q2);
                mma16816(acc[1][3], h0,h1,h2,h3, q1,q3);
            }
        }

        // intra-CTA K-split reduction: kg1 stores, kg0 adds
        if (kg == 1) {
#pragma unroll
            for (int mt = 0; mt < 2; mt++)
#pragma unroll
                for (int nb = 0; nb < 4; nb++) {
                    int b0 = wm + mt * 16 + (lane >> 2);
                    int n0 = wn + nb * 8 + (lane & 3) * 2;
                    float* gp = &gates[n0 * 68 + b0];
                    gp[0]  = acc[mt][nb][0];
                    gp[68] = acc[mt][nb][1];
                    gp[8]  = acc[mt][nb][2];
                    gp[76] = acc[mt][nb][3];
                }
        }
        __syncthreads();
        if (kg == 0) {
#pragma unroll
            for (int mt = 0; mt < 2; mt++)
#pragma unroll
                for (int nb = 0; nb < 4; nb++) {
                    int b0 = wm + mt * 16 + (lane >> 2);
                    int n0 = wn + nb * 8 + (lane & 3) * 2;
                    float* gp = &gates[n0 * 68 + b0];
                    gp[0]  += acc[mt][nb][0];
                    gp[68] += acc[mt][nb][1];
                    gp[8]  += acc[mt][nb][2];
                    gp[76] += acc[mt][nb][3];
                }
        }
        __syncthreads();

        // cross-rank exchange of peer's batch half (8 KB each way) via DSMEM
        dsmem_copy8(xsrc, xdstR);
        cluster_arrive();
        cluster_wait();

        // epilogue: my batch half, 2 cells per thread
        {
            float hv[2];
            __nv_bfloat162 hb;
#pragma unroll
            for (int q = 0; q < 2; q++) {
                int col = jb + q;
                float gi = gates[col * 68 + eb]        + gates2[col * 68 + eb]        + xg[0][q];
                float gf = gates[(col + 16) * 68 + eb] + gates2[(col + 16) * 68 + eb] + xg[1][q];
                float gg = gates[(col + 32) * 68 + eb] + gates2[(col + 32) * 68 + eb] + xg[2][q];
                float go = gates[(col + 48) * 68 + eb] + gates2[(col + 48) * 68 + eb] + xg[3][q];
                float c = sigf(gf) * cst[q] + sigf(gi) * tanhf(gg);
                cst[q] = c;
                float h = sigf(go) * tanhf(c);
                hv[q] = h;
            }
            hb = __floats2bfloat162_rn(hv[0], hv[1]);
            *(unsigned*)&g_h[eb * HDIM + j0 + jb] = *(unsigned*)&hb;
            if (s == S_LEN - 1)
                *(float2*)&g_hf[(size_t)eb * HDIM + j0 + jb] = make_float2(hv[0], hv[1]);
        }

        if (s < S_LEN - 1) {
            // pre-barrier: next step's h-independent prefetches (W_hh + X gates)
            const int tagn = __ldg(tags + s + 1);
            WbRow = g_Whh + (size_t)tagn * G4 * HDIM + wOffB;
            issueW(0); cp_commit();
            issueW(1); cp_commit();
            issueW(2); cp_commit();
            {
                const float* Xs = g_X + (size_t)(s + 1) * G4 * BATCH;
#pragma unroll
                for (int sec = 0; sec < 4; sec++)
#pragma unroll
                    for (int q = 0; q < 2; q++)
                        xg[sec][q] = __ldg(Xs + ((size_t)sec * HDIM + j0 + jb + q) * BATCH + eb);
            }
            __syncthreads();   // all h stores done before the arrival below
            if (tid == 0) {
                __threadfence();
                unsigned target = (unsigned)(s + 1) * NCTA_SEQ;
                unsigned a = atomicAdd(&g_bar, 1u) + 1u;
                if (a < target) {
                    unsigned v;
                    do {
                        asm volatile("ld.global.acquire.gpu.u32 %0, [%1];" : "=r"(v) : "l"(&g_bar));
                    } while (v < target);
                }
            }
            __syncthreads();
            // post-barrier: h-dependent prefetches
            issueA(0); cp_commit();
            issueA(1); cp_commit();
        }
    }
}

// ---------------- K5: MLP head ----------------
__global__ void k_mlp(const float* __restrict__ W1, const float* __restrict__ b1,
                      const float* __restrict__ W2, const float* __restrict__ b2,
                      float* __restrict__ out) {
    __shared__ float red[DFF];
    const int b = blockIdx.x, d = threadIdx.x;
    const float4* h4 = (const float4*)(g_hf + (size_t)b * HDIM);
    const float4* w4 = (const float4*)(W1 + (size_t)d * HDIM);
    float s = 0.f;
#pragma unroll 4
    for (int k = 0; k < HDIM / 4; k++) {
        float4 a = h4[k], w = __ldg(w4 + k);
        s += a.x * w.x + a.y * w.y + a.z * w.z + a.w * w.w;
    }
    float hid = fmaxf(s + __ldg(b1 + d), 0.f);
    red[d] = hid * __ldg(W2 + d);
    __syncthreads();
    for (int st = DFF / 2; st > 0; st >>= 1) {
        if (d < st) red[d] += red[d + st];
        __syncthreads();
    }
    if (d == 0) out[b] = sigf(red[0] + __ldg(b2));
}

// ---------------- launch ----------------
extern "C" void kernel_launch(void* const* d_in, const int* in_sizes, int n_in,
                              void* d_out, int out_size) {
    const int*   tokens = (const int*)d_in[0];
    const int*   tags   = (const int*)d_in[1];
    const float* emb    = (const float*)d_in[2];
    const float* Wih    = (const float*)d_in[3];
    const float* Whh    = (const float*)d_in[4];
    const float* bih    = (const float*)d_in[5];
    const float* bhh    = (const float*)d_in[6];
    const float* W1     = (const float*)d_in[7];
    const float* b1     = (const float*)d_in[8];
    const float* W2     = (const float*)d_in[9];
    const float* b2     = (const float*)d_in[10];
    float* out = (float*)d_out;

    cudaFuncSetAttribute(k_seq, cudaFuncAttributeMaxDynamicSharedMemorySize, SEQ_SMEM);

    k_prep<<<2048, 256>>>((const float4*)Wih, (const float4*)Whh, bih, bhh);
    k_order<<<1, S_LEN>>>(tags);
    k_embed<<<dim3(S_LEN, BATCH), 128>>>(tokens, emb);
    k_xgemm<<<dim3(64, S_LEN), 256>>>(tags);
    k_seq<<<NCTA_SEQ, 256, SEQ_SMEM>>>(tags);
    k_mlp<<<BATCH, DFF>>>(W1, b1, W2, b2, out);
}

// round 6
// speedup vs baseline: 1.3795x; 1.0309x over previous
#include <cuda_runtime.h>
#include <cuda_bf16.h>
#include <cstdint>
#include <cstddef>

#define S_LEN 512
#define BATCH 64
#define EDIM  512
#define HDIM  1024
#define G4    4096
#define NTAGS 13
#define DFF   256
#define NCTA_SEQ 128

// ---------------- persistent device scratch (no allocs allowed) ----------------
__device__ __align__(16) __nv_bfloat16 g_Wih[(size_t)NTAGS * G4 * EDIM];   // 54.5 MB
__device__ __align__(16) __nv_bfloat16 g_Whh[(size_t)NTAGS * G4 * HDIM];   // 109 MB (L2-resident)
__device__ float g_bias[NTAGS * G4];
__device__ __align__(16) __nv_bfloat16 g_x[(size_t)S_LEN * BATCH * EDIM];  // 33.5 MB
__device__ __align__(16) __nv_bfloat16 g_X[(size_t)S_LEN * G4 * BATCH];    // 268 MB input gates (bf16)
__device__ __align__(16) __nv_bfloat16 g_h[BATCH * HDIM];
__device__ float g_hf[BATCH * HDIM];
__device__ int g_order[S_LEN];
__device__ unsigned g_bar2[64];   // [0]: low K-half counter, [32]: high K-half counter

// ---------------- helpers ----------------
__device__ __forceinline__ unsigned smem_u32(const void* p) {
    return (unsigned)__cvta_generic_to_shared(p);
}
__device__ __forceinline__ void cp16(unsigned s, const void* g) {
    asm volatile("cp.async.cg.shared.global [%0], [%1], 16;" :: "r"(s), "l"(g));
}
__device__ __forceinline__ void cp_commit() { asm volatile("cp.async.commit_group;" ::: "memory"); }
__device__ __forceinline__ void cp_waitn(int n) {
    switch (n) {
        case 0: asm volatile("cp.async.wait_group 0;" ::: "memory"); break;
        case 1: asm volatile("cp.async.wait_group 1;" ::: "memory"); break;
        case 2: asm volatile("cp.async.wait_group 2;" ::: "memory"); break;
        default: asm volatile("cp.async.wait_group 3;" ::: "memory"); break;
    }
}
__device__ __forceinline__ void cp_wait1() { asm volatile("cp.async.wait_group 1;" ::: "memory"); }
__device__ __forceinline__ void cp_wait0() { asm volatile("cp.async.wait_group 0;" ::: "memory"); }

__device__ __forceinline__ void ldsm4(unsigned& r0, unsigned& r1, unsigned& r2, unsigned& r3, unsigned a) {
    asm volatile("ldmatrix.sync.aligned.m8n8.x4.shared.b16 {%0,%1,%2,%3}, [%4];"
                 : "=r"(r0), "=r"(r1), "=r"(r2), "=r"(r3) : "r"(a));
}
__device__ __forceinline__ void mma16816(float* c, unsigned a0, unsigned a1, unsigned a2, unsigned a3,
                                         unsigned b0, unsigned b1) {
    asm volatile("mma.sync.aligned.m16n8k16.row.col.f32.bf16.bf16.f32 "
                 "{%0,%1,%2,%3},{%4,%5,%6,%7},{%8,%9},{%0,%1,%2,%3};"
                 : "+f"(c[0]), "+f"(c[1]), "+f"(c[2]), "+f"(c[3])
                 : "r"(a0), "r"(a1), "r"(a2), "r"(a3), "r"(b0), "r"(b1));
}
__device__ __forceinline__ float sigf(float x) { return 1.f / (1.f + __expf(-x)); }

__device__ __forceinline__ uint2 f4_to_bf4(float4 v) {
    __nv_bfloat162 a = __floats2bfloat162_rn(v.x, v.y);
    __nv_bfloat162 b = __floats2bfloat162_rn(v.z, v.w);
    uint2 r;
    r.x = *reinterpret_cast<unsigned*>(&a);
    r.y = *reinterpret_cast<unsigned*>(&b);
    return r;
}

__device__ __forceinline__ unsigned cluster_rank() {
    unsigned r;
    asm("mov.u32 %0, %%cluster_ctarank;" : "=r"(r));
    return r;
}
__device__ __forceinline__ unsigned mapa_rank(unsigned addr, unsigned r) {
    unsigned out;
    asm("mapa.shared::cluster.u32 %0, %1, %2;" : "=r"(out) : "r"(addr), "r"(r));
    return out;
}
__device__ __forceinline__ void cluster_arrive() { asm volatile("barrier.cluster.arrive.aligned;" ::: "memory"); }
__device__ __forceinline__ void cluster_wait()   { asm volatile("barrier.cluster.wait.aligned;" ::: "memory"); }
__device__ __forceinline__ void dsmem_copy8(unsigned lsrc, unsigned rdst) {
#pragma unroll
    for (int i = 0; i < 4; i++) {
        unsigned long long v;
        asm volatile("ld.shared.b64 %0, [%1];" : "=l"(v) : "r"(lsrc + i * 8));
        asm volatile("st.shared::cluster.b64 [%0], %1;" :: "r"(rdst + i * 8), "l"(v) : "memory");
    }
}

// ---------------- K1: weight conversion + state init ----------------
__global__ void k_prep(const float4* __restrict__ Wih, const float4* __restrict__ Whh,
                       const float* __restrict__ bih, const float* __restrict__ bhh) {
    size_t i0 = (size_t)blockIdx.x * blockDim.x + threadIdx.x;
    size_t stp = (size_t)gridDim.x * blockDim.x;
    uint2* wo = (uint2*)g_Wih;
    for (size_t i = i0; i < (size_t)NTAGS * G4 * EDIM / 4; i += stp) wo[i] = f4_to_bf4(__ldg(Wih + i));
    uint2* ho = (uint2*)g_Whh;
    for (size_t i = i0; i < (size_t)NTAGS * G4 * HDIM / 4; i += stp) ho[i] = f4_to_bf4(__ldg(Whh + i));
    for (size_t i = i0; i < (size_t)NTAGS * G4; i += stp) g_bias[i] = bih[i] + bhh[i];
    for (size_t i = i0; i < (size_t)BATCH * HDIM; i += stp) g_h[i] = __float2bfloat16(0.f);
    if (i0 < 64) g_bar2[i0] = 0u;
}

// ---------------- K1b: stable counting sort of steps by tag ----------------
__global__ void k_order(const int* __restrict__ tags) {
    __shared__ int st[S_LEN];
    int t = threadIdx.x;
    st[t] = tags[t];
    __syncthreads();
    int mytag = st[t];
    int rank = 0;
    for (int j = 0; j < S_LEN; j++) {
        int tg = st[j];
        if (tg < mytag || (tg == mytag && j < t)) rank++;
    }
    g_order[rank] = t;
}

// ---------------- K2: embedding gather -> bf16 [S][B][E] ----------------
__global__ void k_embed(const int* __restrict__ tokens, const float* __restrict__ emb) {
    const int s = blockIdx.x, b = blockIdx.y;
    const int tok = __ldg(tokens + b * S_LEN + s);
    float4 v = __ldg((const float4*)(emb + (size_t)tok * EDIM) + threadIdx.x);
    ((uint2*)(g_x + ((size_t)s * BATCH + b) * EDIM))[threadIdx.x] = f4_to_bf4(v);
}

// ---------------- K3: X[s][gate_row][b] = W_ih[tag_s] @ x_s^T + bias (tag-sorted) ----------------
// M=128 tile (grid 32 x S), bf16 output. 8 warps: 4m x 2n, warp tile 32x32.
#define XG_SMEM (36864 + 18432)
__global__ void __launch_bounds__(256) k_xgemm(const int* __restrict__ tags) {
    extern __shared__ __align__(16) unsigned char xsm[];
    __nv_bfloat16* As = (__nv_bfloat16*)xsm;             // [2][128][72]
    __nv_bfloat16* Bs = (__nv_bfloat16*)(xsm + 36864);   // [2][64][72]
    const int s = g_order[blockIdx.y];
    const int rt = blockIdx.x;                            // 0..31
    const int tid = threadIdx.x, lane = tid & 31, wid = tid >> 5;
    const int tag = __ldg(tags + s);
    const __nv_bfloat16* __restrict__ Wb = g_Wih + ((size_t)tag * G4 + rt * 128) * EDIM;
    const __nv_bfloat16* __restrict__ xb = g_x + (size_t)s * BATCH * EDIM;

    const __nv_bfloat16* gsrc[6]; unsigned sdst[6]; unsigned sstr[6];
#pragma unroll
    for (int t = 0; t < 6; t++) {
        if (t < 4) {
            int o = tid + 256 * t, r = o >> 3, sg = o & 7;
            gsrc[t] = Wb + (size_t)r * EDIM + sg * 8;
            sdst[t] = smem_u32(As + r * 72 + sg * 8);
            sstr[t] = 18432u;
        } else {
            int o = tid + 256 * (t - 4), r = o >> 3, sg = o & 7;
            gsrc[t] = xb + (size_t)r * EDIM + sg * 8;
            sdst[t] = smem_u32(Bs + r * 72 + sg * 8);
            sstr[t] = 9216u;
        }
    }
#pragma unroll
    for (int t = 0; t < 6; t++) cp16(sdst[t], gsrc[t]);
    cp_commit();

    const int lr = lane & 15, lc8 = (lane >> 4) * 8;
    const int wm = (wid & 3) * 32, wn = (wid >> 2) * 32;
    const unsigned aLo0 = smem_u32(As + (wm + lr) * 72 + lc8);
    const unsigned aHi0 = aLo0 + 16 * 72 * 2;
    const unsigned bLo0 = smem_u32(Bs + (wn + lr) * 72 + lc8);
    const unsigned bHi0 = bLo0 + 16 * 72 * 2;

    float acc[2][4][4] = {};
    for (int kc = 0; kc < 8; kc++) {
        if (kc < 7) {
#pragma unroll
            for (int t = 0; t < 6; t++)
                cp16(sdst[t] + ((kc + 1) & 1) * sstr[t], gsrc[t] + (kc + 1) * 64);
            cp_commit(); cp_wait1();
        } else cp_wait0();
        __syncthreads();
        const unsigned aOff = (kc & 1) * 18432u, bOff = (kc & 1) * 9216u;
#pragma unroll
        for (int kk = 0; kk < 4; kk++) {
            unsigned ka = aOff + kk * 32u, kb = bOff + kk * 32u;
            unsigned l0,l1,l2,l3, h0,h1,h2,h3, p0,p1,p2,p3, q0,q1,q2,q3;
            ldsm4(l0,l1,l2,l3, aLo0 + ka);
            ldsm4(h0,h1,h2,h3, aHi0 + ka);
            ldsm4(p0,p1,p2,p3, bLo0 + kb);
            ldsm4(q0,q1,q2,q3, bHi0 + kb);
            mma16816(acc[0][0], l0,l1,l2,l3, p0,p2);
            mma16816(acc[0][1], l0,l1,l2,l3, p1,p3);
            mma16816(acc[0][2], l0,l1,l2,l3, q0,q2);
            mma16816(acc[0][3], l0,l1,l2,l3, q1,q3);
            mma16816(acc[1][0], h0,h1,h2,h3, p0,p2);
            mma16816(acc[1][1], h0,h1,h2,h3, p1,p3);
            mma16816(acc[1][2], h0,h1,h2,h3, q0,q2);
            mma16816(acc[1][3], h0,h1,h2,h3, q1,q3);
        }
        __syncthreads();
    }
    const size_t base = (size_t)s * G4;
#pragma unroll
    for (int mt = 0; mt < 2; mt++) {
        int rr = rt * 128 + wm + mt * 16 + (lane >> 2);
        float bb0 = g_bias[tag * G4 + rr];
        float bb1 = g_bias[tag * G4 + rr + 8];
#pragma unroll
        for (int nb = 0; nb < 4; nb++) {
            int cc = wn + nb * 8 + (lane & 3) * 2;
            __nv_bfloat162 v0 = __floats2bfloat162_rn(acc[mt][nb][0] + bb0, acc[mt][nb][1] + bb0);
            __nv_bfloat162 v1 = __floats2bfloat162_rn(acc[mt][nb][2] + bb1, acc[mt][nb][3] + bb1);
            *(__nv_bfloat162*)&g_X[(base + rr) * BATCH + cc]     = v0;
            *(__nv_bfloat162*)&g_X[(base + rr + 8) * BATCH + cc] = v1;
        }
    }
}

// ---------------- K4: persistent sequential LSTM ----------------
// 128 CTAs as 64 clusters of 2; rank = K-half. 8 warps: 2m x 2n x 2kg.
// Per step: 4 W commit-groups pre-barrier, 4 h groups post-barrier,
// pair pr waits cp.async.wait_group (3-pr). Half-split REDG barrier.
#define GATES_OFF  147456
#define GATES2_OFF 164864
#define SEQ_SMEM   182272
__global__ void __launch_bounds__(256) __cluster_dims__(2, 1, 1) k_seq(const int* __restrict__ tags) {
    extern __shared__ __align__(16) unsigned char sm[];
    __nv_bfloat16* As = (__nv_bfloat16*)sm;            // [8][64][72] h tiles
    __nv_bfloat16* Bs = As + 8 * 64 * 72;              // [8][64][72] W tiles
    float* gates  = (float*)(sm + GATES_OFF);          // [64][68]
    float* gates2 = (float*)(sm + GATES2_OFF);         // [64][68]
    const unsigned smb = smem_u32(sm);

    const int tid = threadIdx.x, lane = tid & 31, wid = tid >> 5;
    const unsigned rank = cluster_rank();
    const unsigned peer = rank ^ 1u;
    const int j0 = (blockIdx.x >> 1) * 16;
    const int koff = (int)rank * 512;
    const int kg = wid >> 2;
    const int wq = wid & 3;
    const int wm = (wq & 1) * 32, wn = (wq >> 1) * 32;
    const int myhalf = j0 >> 9;            // which counter I arrive on
    unsigned* const cntArr = g_bar2;

    const int idx = tid * 2;
    const int rT = idx >> 3, sgT = idx & 7;
    const unsigned dA = smem_u32(As + rT * 72 + sgT * 8);
    const unsigned dB = smem_u32(Bs + rT * 72 + sgT * 8);
    const __nv_bfloat16* hRow = g_h + (size_t)rT * HDIM + koff + sgT * 8;
    const size_t wOffB = ((size_t)(j0 + (rT & 15)) + (size_t)(rT >> 4) * HDIM) * HDIM + koff + sgT * 8;

    const int lr = lane & 15, lc8 = (lane >> 4) * 8;
    const unsigned aLo = smem_u32(As + (wm + lr) * 72 + lc8);
    const unsigned aHi = aLo + 16 * 72 * 2;
    const unsigned bLo = smem_u32(Bs + (wn + lr) * 72 + lc8);
    const unsigned bHi = bLo + 16 * 72 * 2;

    const int cn = tid >> 2;
    const int cb = (int)peer * 32 + (tid & 3) * 8;
    const unsigned xsrc = smb + GATES_OFF  + (unsigned)(cn * 68 + cb) * 4;
    const unsigned xdstL = smb + GATES2_OFF + (unsigned)(cn * 68 + cb) * 4;
    const unsigned xdstR = mapa_rank(xdstL, peer);

    const int eb = (int)rank * 32 + lane;
    const int jb = wid * 2;
    float cst[2] = {0.f, 0.f};

    const __nv_bfloat16* WbRow = g_Whh + (size_t)__ldg(tags) * G4 * HDIM + wOffB;

    auto issueW = [&](int pr) {
#pragma unroll
        for (int st2 = 0; st2 < 2; st2++) {
            int kc = 2 * pr + st2;
            unsigned d = dB + (unsigned)kc * 9216u;
            const __nv_bfloat16* sp = WbRow + kc * 64;
            cp16(d, sp); cp16(d + 16, sp + 8);
        }
        cp_commit();
    };
    auto issueA = [&](int pr) {
#pragma unroll
        for (int st2 = 0; st2 < 2; st2++) {
            int kc = 2 * pr + st2;
            unsigned d = dA + (unsigned)kc * 9216u;
            const __nv_bfloat16* sp = hRow + kc * 64;
            cp16(d, sp); cp16(d + 16, sp + 8);
        }
        cp_commit();
    };

    // prologue: all 4 W groups then all 4 A groups (h ready from k_prep)
#pragma unroll
    for (int p = 0; p < 4; p++) issueW(p);
#pragma unroll
    for (int p = 0; p < 4; p++) issueA(p);

    float xg[4][2];
    {
        const __nv_bfloat16* Xs = g_X;
#pragma unroll
        for (int sec = 0; sec < 4; sec++)
#pragma unroll
            for (int q = 0; q < 2; q++)
                xg[sec][q] = __bfloat162float(__ldg(Xs + ((size_t)sec * HDIM + j0 + jb + q) * BATCH + eb));
    }

#pragma unroll 1
    for (int s = 0; s < S_LEN; s++) {
        float acc[2][4][4];
#pragma unroll
        for (int a = 0; a < 2; a++)
#pragma unroll
            for (int b = 0; b < 4; b++)
#pragma unroll
                for (int c = 0; c < 4; c++) acc[a][b][c] = 0.f;

#pragma unroll 1
        for (int pr = 0; pr < 4; pr++) {
            cp_waitn(3 - pr);
            __syncthreads();
            const int kc = 2 * pr + kg;
            const unsigned so = (unsigned)kc * 9216u;
#pragma unroll
            for (int kk = 0; kk < 4; kk++) {
                unsigned ko = so + kk * 32u;
                unsigned l0,l1,l2,l3, h0,h1,h2,h3, p0,p1,p2,p3, q0,q1,q2,q3;
                ldsm4(l0,l1,l2,l3, aLo + ko);
                ldsm4(h0,h1,h2,h3, aHi + ko);
                ldsm4(p0,p1,p2,p3, bLo + ko);
                ldsm4(q0,q1,q2,q3, bHi + ko);
                mma16816(acc[0][0], l0,l1,l2,l3, p0,p2);
                mma16816(acc[0][1], l0,l1,l2,l3, p1,p3);
                mma16816(acc[0][2], l0,l1,l2,l3, q0,q2);
                mma16816(acc[0][3], l0,l1,l2,l3, q1,q3);
                mma16816(acc[1][0], h0,h1,h2,h3, p0,p2);
                mma16816(acc[1][1], h0,h1,h2,h3, p1,p3);
                mma16816(acc[1][2], h0,h1,h2,h3, q0,q2);
                mma16816(acc[1][3], h0,h1,h2,h3, q1,q3);
            }
        }

        // intra-CTA K-split reduction
        if (kg == 1) {
#pragma unroll
            for (int mt = 0; mt < 2; mt++)
#pragma unroll
                for (int nb = 0; nb < 4; nb++) {
                    int b0 = wm + mt * 16 + (lane >> 2);
                    int n0 = wn + nb * 8 + (lane & 3) * 2;
                    float* gp = &gates[n0 * 68 + b0];
                    gp[0]  = acc[mt][nb][0];
                    gp[68] = acc[mt][nb][1];
                    gp[8]  = acc[mt][nb][2];
                    gp[76] = acc[mt][nb][3];
                }
        }
        __syncthreads();
        if (kg == 0) {
#pragma unroll
            for (int mt = 0; mt < 2; mt++)
#pragma unroll
                for (int nb = 0; nb < 4; nb++) {
                    int b0 = wm + mt * 16 + (lane >> 2);
                    int n0 = wn + nb * 8 + (lane & 3) * 2;
                    float* gp = &gates[n0 * 68 + b0];
                    gp[0]  += acc[mt][nb][0];
                    gp[68] += acc[mt][nb][1];
                    gp[8]  += acc[mt][nb][2];
                    gp[76] += acc[mt][nb][3];
                }
        }
        __syncthreads();

        // cross-rank exchange of peer's batch half via DSMEM
        dsmem_copy8(xsrc, xdstR);
        cluster_arrive();
        cluster_wait();

        // epilogue: my batch half, 2 cells per thread
        {
            float hv[2];
#pragma unroll
            for (int q = 0; q < 2; q++) {
                int col = jb + q;
                float gi = gates[col * 68 + eb]        + gates2[col * 68 + eb]        + xg[0][q];
                float gf = gates[(col + 16) * 68 + eb] + gates2[(col + 16) * 68 + eb] + xg[1][q];
                float gg = gates[(col + 32) * 68 + eb] + gates2[(col + 32) * 68 + eb] + xg[2][q];
                float go = gates[(col + 48) * 68 + eb] + gates2[(col + 48) * 68 + eb] + xg[3][q];
                float c = sigf(gf) * cst[q] + sigf(gi) * tanhf(gg);
                cst[q] = c;
                hv[q] = sigf(go) * tanhf(c);
            }
            __nv_bfloat162 hb = __floats2bfloat162_rn(hv[0], hv[1]);
            *(unsigned*)&g_h[eb * HDIM + j0 + jb] = *(unsigned*)&hb;
            if (s == S_LEN - 1)
                *(float2*)&g_hf[(size_t)eb * HDIM + j0 + jb] = make_float2(hv[0], hv[1]);
        }

        if (s < S_LEN - 1) {
            // pre-barrier: next step's h-independent prefetches (W groups + X gates)
            const int tagn = __ldg(tags + s + 1);
            WbRow = g_Whh + (size_t)tagn * G4 * HDIM + wOffB;
#pragma unroll
            for (int p = 0; p < 4; p++) issueW(p);
            {
                const __nv_bfloat16* Xs = g_X + (size_t)(s + 1) * G4 * BATCH;
#pragma unroll
                for (int sec = 0; sec < 4; sec++)
#pragma unroll
                    for (int q = 0; q < 2; q++)
                        xg[sec][q] = __bfloat162float(__ldg(Xs + ((size_t)sec * HDIM + j0 + jb + q) * BATCH + eb));
            }
            __syncthreads();   // all h stores done before arrival
            if (tid == 0) {
                __threadfence();
                asm volatile("red.global.add.u32 [%0], 1;" :: "l"(cntArr + myhalf * 32) : "memory");
                unsigned target = (unsigned)(s + 1) * 64u;
                unsigned v;
                do {
                    asm volatile("ld.global.acquire.gpu.u32 %0, [%1];" : "=r"(v) : "l"(cntArr + (int)rank * 32));
                } while (v < target);
            }
            __syncthreads();
            // post-barrier: all 4 h-dependent groups
#pragma unroll
            for (int p = 0; p < 4; p++) issueA(p);
        }
    }
}

// ---------------- K5: MLP head ----------------
__global__ void k_mlp(const float* __restrict__ W1, const float* __restrict__ b1,
                      const float* __restrict__ W2, const float* __restrict__ b2,
                      float* __restrict__ out) {
    __shared__ float red[DFF];
    const int b = blockIdx.x, d = threadIdx.x;
    const float4* h4 = (const float4*)(g_hf + (size_t)b * HDIM);
    const float4* w4 = (const float4*)(W1 + (size_t)d * HDIM);
    float s = 0.f;
#pragma unroll 4
    for (int k = 0; k < HDIM / 4; k++) {
        float4 a = h4[k], w = __ldg(w4 + k);
        s += a.x * w.x + a.y * w.y + a.z * w.z + a.w * w.w;
    }
    float hid = fmaxf(s + __ldg(b1 + d), 0.f);
    red[d] = hid * __ldg(W2 + d);
    __syncthreads();
    for (int st = DFF / 2; st > 0; st >>= 1) {
        if (d < st) red[d] += red[d + st];
        __syncthreads();
    }
    if (d == 0) out[b] = sigf(red[0] + __ldg(b2));
}

// ---------------- launch ----------------
extern "C" void kernel_launch(void* const* d_in, const int* in_sizes, int n_in,
                              void* d_out, int out_size) {
    const int*   tokens = (const int*)d_in[0];
    const int*   tags   = (const int*)d_in[1];
    const float* emb    = (const float*)d_in[2];
    const float* Wih    = (const float*)d_in[3];
    const float* Whh    = (const float*)d_in[4];
    const float* bih    = (const float*)d_in[5];
    const float* bhh    = (const float*)d_in[6];
    const float* W1     = (const float*)d_in[7];
    const float* b1     = (const float*)d_in[8];
    const float* W2     = (const float*)d_in[9];
    const float* b2     = (const float*)d_in[10];
    float* out = (float*)d_out;

    cudaFuncSetAttribute(k_seq, cudaFuncAttributeMaxDynamicSharedMemorySize, SEQ_SMEM);
    cudaFuncSetAttribute(k_xgemm, cudaFuncAttributeMaxDynamicSharedMemorySize, XG_SMEM);

    k_prep<<<2048, 256>>>((const float4*)Wih, (const float4*)Whh, bih, bhh);
    k_order<<<1, S_LEN>>>(tags);
    k_embed<<<dim3(S_LEN, BATCH), 128>>>(tokens, emb);
    k_xgemm<<<dim3(32, S_LEN), 256, XG_SMEM>>>(tags);
    k_seq<<<NCTA_SEQ, 256, SEQ_SMEM>>>(tags);
    k_mlp<<<BATCH, DFF>>>(W1, b1, W2, b2, out);
}